// round 12
// baseline (speedup 1.0000x reference)
#include <cuda_runtime.h>
#include <cstdint>

// Problem constants: B=64, C=128, M=H*W=4096, fp32 in/out
#define BB 64
#define CC 128
#define MM 4096
#define KS 2                    // split-K across CTAs
#define KCHUNK (MM / KS)        // 2048
#define KTILE 64                // bf16 k per stage
#define NSTAGE (KCHUNK / KTILE) // 32
#define PITCH 144               // smem row pitch bytes (128B data + 16B pad)
#define TILEB (CC * PITCH)      // 18432 bytes per bf16 tile
#define SPITCH 132              // fp32 transpose buffer pitch (floats)
#define SMEM_BYTES (4 * TILEB)  // 73728 >= 128*132*4 S overlay
#define NTH 512                 // 16 warps, 32x32 tile each

// ---------------- scratch (__device__ globals; no allocs allowed) ----------
__device__ float g_sum[KS * BB * CC];            // per-(ks,b,c) row sums
__device__ float g_part[KS * BB * CC * CC];      // per-ks S = P + Q + Q^T

// ---------------- helpers ---------------------------------------------------
__device__ __forceinline__ uint32_t smem_u32(const void* p) {
    uint32_t a;
    asm("{ .reg .u64 t; cvta.to.shared.u64 t, %1; cvt.u32.u64 %0, t; }"
        : "=r"(a) : "l"(p));
    return a;
}
__device__ __forceinline__ void ldsm_x4(uint32_t& r0, uint32_t& r1,
                                        uint32_t& r2, uint32_t& r3, uint32_t a) {
    asm volatile("ldmatrix.sync.aligned.m8n8.x4.shared.b16 {%0,%1,%2,%3}, [%4];"
                 : "=r"(r0), "=r"(r1), "=r"(r2), "=r"(r3) : "r"(a));
}
__device__ __forceinline__ void mma_bf16(float* d, const uint32_t* a,
                                         uint32_t b0, uint32_t b1) {
    asm volatile(
        "mma.sync.aligned.m16n8k16.row.col.f32.bf16.bf16.f32 "
        "{%0,%1,%2,%3}, {%4,%5,%6,%7}, {%8,%9}, {%0,%1,%2,%3};"
        : "+f"(d[0]), "+f"(d[1]), "+f"(d[2]), "+f"(d[3])
        : "r"(a[0]), "r"(a[1]), "r"(a[2]), "r"(a[3]), "r"(b0), "r"(b1));
}

// convert one float4 (4 elems of a row) to hi/lo bf16 pairs and store to smem
__device__ __forceinline__ void convert_store(const float4 xv, int row, int kseg,
                                              uint32_t hibase, uint32_t lobase,
                                              float& rsum) {
    rsum += (xv.x + xv.y) + (xv.z + xv.w);
    uint32_t h01, h23, l01, l23;
    asm("cvt.rn.bf16x2.f32 %0, %1, %2;" : "=r"(h01) : "f"(xv.y), "f"(xv.x));
    asm("cvt.rn.bf16x2.f32 %0, %1, %2;" : "=r"(h23) : "f"(xv.w), "f"(xv.z));
    const float hx = __uint_as_float(h01 << 16);
    const float hy = __uint_as_float(h01 & 0xffff0000u);
    const float hz = __uint_as_float(h23 << 16);
    const float hw = __uint_as_float(h23 & 0xffff0000u);
    asm("cvt.rn.bf16x2.f32 %0, %1, %2;" : "=r"(l01) : "f"(xv.y - hy), "f"(xv.x - hx));
    asm("cvt.rn.bf16x2.f32 %0, %1, %2;" : "=r"(l23) : "f"(xv.w - hw), "f"(xv.z - hz));
    const uint32_t off = (uint32_t)row * PITCH + (uint32_t)kseg * 8;
    asm volatile("st.shared.v2.b32 [%0], {%1,%2};"
                 :: "r"(hibase + off), "r"(h01), "r"(h23));
    asm volatile("st.shared.v2.b32 [%0], {%1,%2};"
                 :: "r"(lobase + off), "r"(l01), "r"(l23));
}

// ---------------------------------------------------------------------------
// SYRK via bf16-split mma.sync, two-term (P = hi*hi^T, Q = hi*lo^T).
// 512 threads / 16 warps, 32x32 output tile per warp -> 4 warps per SMSP for
// latency hiding; phase-separated convert/MMA with one barrier per stage.
// Q + Q^T folded in-CTA via a single-phase full smem transpose.
// grid = (KS, BB).
// ---------------------------------------------------------------------------
__global__ void __launch_bounds__(NTH, 1) syrk_mma(const float* __restrict__ x) {
    extern __shared__ __align__(128) uint8_t smraw[];
    uint8_t (*tiles)[2 * TILEB] = reinterpret_cast<uint8_t (*)[2 * TILEB]>(smraw);
    float (*S)[SPITCH] = reinterpret_cast<float (*)[SPITCH]>(smraw);

    const int tid = threadIdx.x;
    const int wid = tid >> 5;
    const int lid = tid & 31;
    const int b = blockIdx.y;
    const int ks = blockIdx.x;
    const float* xb = x + (size_t)b * CC * MM + ks * KCHUNK;

    const int rw = (wid >> 2) * 32;   // warp row base (ti)
    const int cw = (wid & 3) * 32;    // warp col base (tj)

    float accP[2][4][4], accQ[2][4][4];
    #pragma unroll
    for (int mb = 0; mb < 2; mb++)
        #pragma unroll
        for (int jb = 0; jb < 4; jb++)
            #pragma unroll
            for (int q = 0; q < 4; q++) { accP[mb][jb][q] = 0.0f; accQ[mb][jb][q] = 0.0f; }

    float rs[4] = {0.f, 0.f, 0.f, 0.f};

    // loader mapping: 16 k-segments (float4) per row, 32 row groups of 4 rows
    const int rowq = tid >> 4;        // 0..31
    const int kseg = tid & 15;        // 0..15

    // ldmatrix lane byte-offsets inside a tile
    const uint32_t a_row_off = ((lid & 7) + ((lid >> 3) & 1) * 8) * PITCH
                             + ((lid >> 4) * 8) * 2;
    const uint32_t b4_row_off = ((lid & 7) + (lid >> 4) * 8) * PITCH
                              + (((lid >> 3) & 1) * 8) * 2;

    float4 v[4];
    #pragma unroll
    for (int it = 0; it < 4; it++)
        v[it] = *reinterpret_cast<const float4*>(
            xb + (size_t)(it * 32 + rowq) * MM + kseg * 4);

    for (int s = 0; s < NSTAGE; s++) {
        const int buf = s & 1;
        const uint32_t hibase = smem_u32(&tiles[buf][0]);
        const uint32_t lobase = hibase + TILEB;

        // convert current regs -> smem tiles, accumulate row sums
        #pragma unroll
        for (int it = 0; it < 4; it++)
            convert_store(v[it], it * 32 + rowq, kseg, hibase, lobase, rs[it]);

        // issue next stage's global loads before the barrier (v is dead here)
        if (s + 1 < NSTAGE) {
            const int k0 = (s + 1) * KTILE;
            #pragma unroll
            for (int it = 0; it < 4; it++)
                v[it] = *reinterpret_cast<const float4*>(
                    xb + (size_t)(it * 32 + rowq) * MM + k0 + kseg * 4);
        }
        // Single barrier per stage (double buffering covers the WAR hazard).
        __syncthreads();

        // compute: 4 k16 steps; A is always hi; B fragments via x4 (n16 each)
        #pragma unroll
        for (int kb = 0; kb < 4; kb++) {
            uint32_t ah[2][4];
            #pragma unroll
            for (int mb = 0; mb < 2; mb++) {
                const uint32_t aoff = (rw + mb * 16) * PITCH + kb * 32 + a_row_off;
                ldsm_x4(ah[mb][0], ah[mb][1], ah[mb][2], ah[mb][3], hibase + aoff);
            }
            #pragma unroll
            for (int jbp = 0; jbp < 2; jbp++) {
                const uint32_t boff = (cw + jbp * 16) * PITCH + kb * 32 + b4_row_off;
                uint32_t bh0, bh1, bh2, bh3, bl0, bl1, bl2, bl3;
                ldsm_x4(bh0, bh1, bh2, bh3, hibase + boff);
                ldsm_x4(bl0, bl1, bl2, bl3, lobase + boff);
                #pragma unroll
                for (int mb = 0; mb < 2; mb++) {
                    mma_bf16(accP[mb][2 * jbp + 0], ah[mb], bh0, bh1);
                    mma_bf16(accP[mb][2 * jbp + 1], ah[mb], bh2, bh3);
                    mma_bf16(accQ[mb][2 * jbp + 0], ah[mb], bl0, bl1);
                    mma_bf16(accQ[mb][2 * jbp + 1], ah[mb], bl2, bl3);
                }
            }
        }
    }

    // row sums: 16 lanes (same rowq) share a row; reduce over kseg, store per ks
    #pragma unroll
    for (int it = 0; it < 4; it++) {
        float vv = rs[it];
        vv += __shfl_xor_sync(0xffffffffu, vv, 8);
        vv += __shfl_xor_sync(0xffffffffu, vv, 4);
        vv += __shfl_xor_sync(0xffffffffu, vv, 2);
        vv += __shfl_xor_sync(0xffffffffu, vv, 1);
        if (kseg == 0)
            g_sum[ks * BB * CC + b * CC + it * 32 + rowq] = vv;
    }

    // ---- Q + Q^T fold via single-phase full smem transpose ------------------
    const int g = lid >> 2;            // 0..7
    const int tg = lid & 3;            // 0..3
    __syncthreads();                   // last-stage ldsm done before S overlay
    #pragma unroll
    for (int mb = 0; mb < 2; mb++)
        #pragma unroll
        for (int jb = 0; jb < 4; jb++) {
            const int row = rw + mb * 16 + g;
            const int cl = cw + jb * 8 + tg * 2;
            S[row][cl]         = accQ[mb][jb][0];
            S[row][cl + 1]     = accQ[mb][jb][1];
            S[row + 8][cl]     = accQ[mb][jb][2];
            S[row + 8][cl + 1] = accQ[mb][jb][3];
        }
    __syncthreads();
    #pragma unroll
    for (int mb = 0; mb < 2; mb++)
        #pragma unroll
        for (int jb = 0; jb < 4; jb++) {
            const int C = cw + jb * 8 + tg * 2;
            const int R0 = rw + mb * 16 + g;
            accP[mb][jb][0] += S[C][R0];
            accP[mb][jb][1] += S[C + 1][R0];
            accP[mb][jb][2] += S[C][R0 + 8];
            accP[mb][jb][3] += S[C + 1][R0 + 8];
        }

    // epilogue: write S = P + Q^T(accumulated) + Q
    float* dst = g_part + (size_t)(ks * BB + b) * (CC * CC);
    #pragma unroll
    for (int mb = 0; mb < 2; mb++) {
        #pragma unroll
        for (int jb = 0; jb < 4; jb++) {
            const int row = rw + mb * 16 + g;
            const int col = cw + jb * 8 + tg * 2;
            *reinterpret_cast<float2*>(&dst[(size_t)row * CC + col]) =
                make_float2(accP[mb][jb][0] + accQ[mb][jb][0],
                            accP[mb][jb][1] + accQ[mb][jb][1]);
            *reinterpret_cast<float2*>(&dst[(size_t)(row + 8) * CC + col]) =
                make_float2(accP[mb][jb][2] + accQ[mb][jb][2],
                            accP[mb][jb][3] + accQ[mb][jb][3]);
        }
    }
}

// ---------------------------------------------------------------------------
// out[b][r][c] = (S0 + S1)/M - mu_r * mu_c  (per-block smem-cached mu)
// ---------------------------------------------------------------------------
__global__ void __launch_bounds__(256) finalize(float* __restrict__ out) {
    __shared__ float smu[CC];
    const int i = blockIdx.x * blockDim.x + threadIdx.x;    // float4 index
    const int base = i * 4;
    const int b = base >> 14;                                // fixed per block
    const float inv = 1.0f / (float)MM;

    if (threadIdx.x < CC)
        smu[threadIdx.x] = (g_sum[b * CC + threadIdx.x]
                          + g_sum[BB * CC + b * CC + threadIdx.x]) * inv;
    __syncthreads();

    const int r = (base >> 7) & (CC - 1);
    const int c = base & (CC - 1);

    const float4 s0 = reinterpret_cast<const float4*>(g_part)[i];
    const float4 s1 = reinterpret_cast<const float4*>(g_part)[BB * CC * CC / 4 + i];

    const float mur = smu[r];
    float4 o;
    o.x = (s0.x + s1.x) * inv - mur * smu[c + 0];
    o.y = (s0.y + s1.y) * inv - mur * smu[c + 1];
    o.z = (s0.z + s1.z) * inv - mur * smu[c + 2];
    o.w = (s0.w + s1.w) * inv - mur * smu[c + 3];
    reinterpret_cast<float4*>(out)[i] = o;
}

// ---------------------------------------------------------------------------
extern "C" void kernel_launch(void* const* d_in, const int* in_sizes, int n_in,
                              void* d_out, int out_size) {
    const float* x = (const float*)d_in[0];
    float* out = (float*)d_out;

    cudaFuncSetAttribute(syrk_mma, cudaFuncAttributeMaxDynamicSharedMemorySize,
                         SMEM_BYTES);

    dim3 grid(KS, BB);
    syrk_mma<<<grid, NTH, SMEM_BYTES>>>(x);
    finalize<<<(BB * CC * CC / 4) / 256, 256>>>(out);
}

// round 13
// speedup vs baseline: 1.0879x; 1.0879x over previous
#include <cuda_runtime.h>
#include <cstdint>

// Problem constants: B=64, C=128, M=H*W=4096, fp32 in/out
#define BB 64
#define CC 128
#define MM 4096
#define KS 2                    // split-K across CTAs
#define KCHUNK (MM / KS)        // 2048
#define KTILE 64                // bf16 k per stage
#define NSTAGE (KCHUNK / KTILE) // 32
#define PITCH 144               // smem row pitch bytes (128B data + 16B pad)
#define TILEB (CC * PITCH)      // 18432 bytes per bf16 tile
#define SPITCH 72               // transpose buffer pitch (floats)
#define SMEM_BYTES (4 * TILEB)  // 73728: 2 bufs x (hi+lo); S overlay fits

// ---------------- scratch (__device__ globals; no allocs allowed) ----------
__device__ float g_sum[KS * 2 * BB * CC];        // per-(ks,group,b,c) row sums
__device__ float g_part[KS * BB * CC * CC];      // per-ks S = P + Q + Q^T

// ---------------- helpers ---------------------------------------------------
__device__ __forceinline__ uint32_t smem_u32(const void* p) {
    uint32_t a;
    asm("{ .reg .u64 t; cvta.to.shared.u64 t, %1; cvt.u32.u64 %0, t; }"
        : "=r"(a) : "l"(p));
    return a;
}
__device__ __forceinline__ void ldsm_x4(uint32_t& r0, uint32_t& r1,
                                        uint32_t& r2, uint32_t& r3, uint32_t a) {
    asm volatile("ldmatrix.sync.aligned.m8n8.x4.shared.b16 {%0,%1,%2,%3}, [%4];"
                 : "=r"(r0), "=r"(r1), "=r"(r2), "=r"(r3) : "r"(a));
}
__device__ __forceinline__ void mma_bf16(float* d, const uint32_t* a,
                                         uint32_t b0, uint32_t b1) {
    asm volatile(
        "mma.sync.aligned.m16n8k16.row.col.f32.bf16.bf16.f32 "
        "{%0,%1,%2,%3}, {%4,%5,%6,%7}, {%8,%9}, {%0,%1,%2,%3};"
        : "+f"(d[0]), "+f"(d[1]), "+f"(d[2]), "+f"(d[3])
        : "r"(a[0]), "r"(a[1]), "r"(a[2]), "r"(a[3]), "r"(b0), "r"(b1));
}

// convert one float4 (4 elems of a row) to hi/lo bf16 pairs and store to smem
__device__ __forceinline__ void convert_store(const float4 xv, int row, int kseg,
                                              uint32_t hibase, uint32_t lobase,
                                              float& rsum) {
    rsum += (xv.x + xv.y) + (xv.z + xv.w);
    uint32_t h01, h23, l01, l23;
    asm("cvt.rn.bf16x2.f32 %0, %1, %2;" : "=r"(h01) : "f"(xv.y), "f"(xv.x));
    asm("cvt.rn.bf16x2.f32 %0, %1, %2;" : "=r"(h23) : "f"(xv.w), "f"(xv.z));
    const float hx = __uint_as_float(h01 << 16);
    const float hy = __uint_as_float(h01 & 0xffff0000u);
    const float hz = __uint_as_float(h23 << 16);
    const float hw = __uint_as_float(h23 & 0xffff0000u);
    asm("cvt.rn.bf16x2.f32 %0, %1, %2;" : "=r"(l01) : "f"(xv.y - hy), "f"(xv.x - hx));
    asm("cvt.rn.bf16x2.f32 %0, %1, %2;" : "=r"(l23) : "f"(xv.w - hw), "f"(xv.z - hz));
    const uint32_t off = (uint32_t)row * PITCH + (uint32_t)kseg * 8;
    asm volatile("st.shared.v2.b32 [%0], {%1,%2};"
                 :: "r"(hibase + off), "r"(h01), "r"(h23));
    asm volatile("st.shared.v2.b32 [%0], {%1,%2};"
                 :: "r"(lobase + off), "r"(l01), "r"(l23));
}

// ---------------------------------------------------------------------------
// SYRK via bf16-split mma.sync, two-term (P = hi*hi^T, Q = hi*lo^T).
// Round-8 skeleton (256 thr, 8 warps, 32x64 tiles) with ALTERNATING-GROUP
// conversion: during stage s, warp-group ((s&1)^1) LDGs + converts stage s+1
// (whole tile) then runs its MMAs; the other group runs MMAs immediately.
// On each SMSP one warp streams HMMA while the other converts -> overlap via
// the warp arbiter, no extra registers, one barrier per stage.
// grid = (KS, BB).
// ---------------------------------------------------------------------------
__global__ void __launch_bounds__(256, 1) syrk_mma(const float* __restrict__ x) {
    extern __shared__ __align__(128) uint8_t smraw[];
    uint8_t (*tiles)[2 * TILEB] = reinterpret_cast<uint8_t (*)[2 * TILEB]>(smraw);
    float (*S)[SPITCH] = reinterpret_cast<float (*)[SPITCH]>(smraw);

    const int tid = threadIdx.x;
    const int wid = tid >> 5;
    const int lid = tid & 31;
    const int group = tid >> 7;       // 0: warps 0-3, 1: warps 4-7
    const int b = blockIdx.y;
    const int ks = blockIdx.x;
    const float* xb = x + (size_t)b * CC * MM + ks * KCHUNK;

    const int rw = (wid >> 1) * 32;   // warp row base in 128x128 output
    const int cw = (wid & 1) * 64;    // warp col base

    float accP[2][8][4], accQ[2][8][4];
    #pragma unroll
    for (int mb = 0; mb < 2; mb++)
        #pragma unroll
        for (int jb = 0; jb < 8; jb++)
            #pragma unroll
            for (int q = 0; q < 4; q++) { accP[mb][jb][q] = 0.0f; accQ[mb][jb][q] = 0.0f; }

    float rs[16];
    #pragma unroll
    for (int i = 0; i < 16; i++) rs[i] = 0.f;

    // convert mapping within a 128-thread group: 16 ksegs x 8 row-subgroups;
    // iteration it covers row = it*8 + rowg8 (16 its -> 128 rows)
    const int gt = tid & 127;
    const int rowg8 = gt >> 4;        // 0..7
    const int kseg = gt & 15;         // 0..15

    // ldmatrix lane byte-offsets inside a tile
    const uint32_t a_row_off = ((lid & 7) + ((lid >> 3) & 1) * 8) * PITCH
                             + ((lid >> 4) * 8) * 2;
    const uint32_t b4_row_off = ((lid & 7) + (lid >> 4) * 8) * PITCH
                              + (((lid >> 3) & 1) * 8) * 2;

    // ---- prologue: group 0 converts stage 0 into buf0 ----------------------
    if (group == 0) {
        const uint32_t h0 = smem_u32(&tiles[0][0]);
        const uint32_t l0 = h0 + TILEB;
        #pragma unroll
        for (int half = 0; half < 2; half++) {
            float4 v[8];
            #pragma unroll
            for (int i = 0; i < 8; i++)
                v[i] = *reinterpret_cast<const float4*>(
                    xb + (size_t)((half * 8 + i) * 8 + rowg8) * MM + kseg * 4);
            #pragma unroll
            for (int i = 0; i < 8; i++)
                convert_store(v[i], (half * 8 + i) * 8 + rowg8, kseg,
                              h0, l0, rs[half * 8 + i]);
        }
    }
    __syncthreads();

    for (int s = 0; s < NSTAGE; s++) {
        const int buf = s & 1;
        const uint32_t hibase = smem_u32(&tiles[buf][0]);
        const uint32_t lobase = hibase + TILEB;

        // converting group handles stage s+1 first (LDG latency + cvt chain
        // hides under the other group's HMMA stream on the same SMSP)
        if (group == ((s & 1) ^ 1) && s + 1 < NSTAGE) {
            const uint32_t nhib = smem_u32(&tiles[buf ^ 1][0]);
            const uint32_t nlob = nhib + TILEB;
            const int k0 = (s + 1) * KTILE;
            #pragma unroll
            for (int half = 0; half < 2; half++) {
                float4 v[8];
                #pragma unroll
                for (int i = 0; i < 8; i++)
                    v[i] = *reinterpret_cast<const float4*>(
                        xb + (size_t)((half * 8 + i) * 8 + rowg8) * MM + k0 + kseg * 4);
                #pragma unroll
                for (int i = 0; i < 8; i++)
                    convert_store(v[i], (half * 8 + i) * 8 + rowg8, kseg,
                                  nhib, nlob, rs[half * 8 + i]);
            }
        }

        // all warps: 4 k16 MMA blocks on buf
        #pragma unroll
        for (int kb = 0; kb < 4; kb++) {
            uint32_t ah[2][4];
            #pragma unroll
            for (int mb = 0; mb < 2; mb++) {
                const uint32_t aoff = (rw + mb * 16) * PITCH + kb * 32 + a_row_off;
                ldsm_x4(ah[mb][0], ah[mb][1], ah[mb][2], ah[mb][3], hibase + aoff);
            }
            #pragma unroll
            for (int jbp = 0; jbp < 4; jbp++) {
                const uint32_t boff = (cw + jbp * 16) * PITCH + kb * 32 + b4_row_off;
                uint32_t bh0, bh1, bh2, bh3, bl0, bl1, bl2, bl3;
                ldsm_x4(bh0, bh1, bh2, bh3, hibase + boff);
                ldsm_x4(bl0, bl1, bl2, bl3, lobase + boff);
                #pragma unroll
                for (int mb = 0; mb < 2; mb++) {
                    mma_bf16(accP[mb][2 * jbp + 0], ah[mb], bh0, bh1);
                    mma_bf16(accP[mb][2 * jbp + 1], ah[mb], bh2, bh3);
                    mma_bf16(accQ[mb][2 * jbp + 0], ah[mb], bl0, bl1);
                    mma_bf16(accQ[mb][2 * jbp + 1], ah[mb], bl2, bl3);
                }
            }
        }
        __syncthreads();
    }

    // row sums: within a group, 16 threads (same rowg8) share each row; each
    // group owns its converted stages -> separate slice of g_sum
    #pragma unroll
    for (int it = 0; it < 16; it++) {
        float vv = rs[it];
        vv += __shfl_xor_sync(0xffffffffu, vv, 8);
        vv += __shfl_xor_sync(0xffffffffu, vv, 4);
        vv += __shfl_xor_sync(0xffffffffu, vv, 2);
        vv += __shfl_xor_sync(0xffffffffu, vv, 1);
        if (kseg == 0)
            g_sum[(ks * 2 + group) * BB * CC + b * CC + it * 8 + rowg8] = vv;
    }

    // ---- Q + Q^T fold via smem transpose (2 column-half phases) ------------
    const int g = lid >> 2;            // 0..7
    const int tg = lid & 3;            // 0..3
    __syncthreads();                   // last-stage ldsm done before S overlay
    #pragma unroll
    for (int h = 0; h < 2; h++) {
        if ((wid & 1) == h) {
            #pragma unroll
            for (int mb = 0; mb < 2; mb++)
                #pragma unroll
                for (int jb = 0; jb < 8; jb++) {
                    const int row = rw + mb * 16 + g;
                    const int cl = jb * 8 + tg * 2;
                    S[row][cl]         = accQ[mb][jb][0];
                    S[row][cl + 1]     = accQ[mb][jb][1];
                    S[row + 8][cl]     = accQ[mb][jb][2];
                    S[row + 8][cl + 1] = accQ[mb][jb][3];
                }
        }
        __syncthreads();
        if ((wid >> 2) == h) {
            #pragma unroll
            for (int mb = 0; mb < 2; mb++)
                #pragma unroll
                for (int jb = 0; jb < 8; jb++) {
                    const int C = cw + jb * 8 + tg * 2;
                    const int R0 = (rw + mb * 16 + g) & 63;
                    accP[mb][jb][0] += S[C][R0];
                    accP[mb][jb][1] += S[C + 1][R0];
                    accP[mb][jb][2] += S[C][R0 + 8];
                    accP[mb][jb][3] += S[C + 1][R0 + 8];
                }
        }
        __syncthreads();
    }

    // epilogue: write S = P + Q^T(accumulated) + Q
    float* dst = g_part + (size_t)(ks * BB + b) * (CC * CC);
    #pragma unroll
    for (int mb = 0; mb < 2; mb++) {
        #pragma unroll
        for (int jb = 0; jb < 8; jb++) {
            const int row = rw + mb * 16 + g;
            const int col = cw + jb * 8 + tg * 2;
            *reinterpret_cast<float2*>(&dst[(size_t)row * CC + col]) =
                make_float2(accP[mb][jb][0] + accQ[mb][jb][0],
                            accP[mb][jb][1] + accQ[mb][jb][1]);
            *reinterpret_cast<float2*>(&dst[(size_t)(row + 8) * CC + col]) =
                make_float2(accP[mb][jb][2] + accQ[mb][jb][2],
                            accP[mb][jb][3] + accQ[mb][jb][3]);
        }
    }
}

// ---------------------------------------------------------------------------
// out[b][r][c] = (S0 + S1)/M - mu_r * mu_c  (per-block smem-cached mu; mu is
// the sum of 4 slices: ks x group)
// ---------------------------------------------------------------------------
__global__ void __launch_bounds__(256) finalize(float* __restrict__ out) {
    __shared__ float smu[CC];
    const int i = blockIdx.x * blockDim.x + threadIdx.x;    // float4 index
    const int base = i * 4;
    const int b = base >> 14;                                // fixed per block
    const float inv = 1.0f / (float)MM;

    if (threadIdx.x < CC) {
        const int o = b * CC + threadIdx.x;
        smu[threadIdx.x] = (g_sum[o] + g_sum[BB * CC + o]
                          + g_sum[2 * BB * CC + o] + g_sum[3 * BB * CC + o]) * inv;
    }
    __syncthreads();

    const int r = (base >> 7) & (CC - 1);
    const int c = base & (CC - 1);

    const float4 s0 = reinterpret_cast<const float4*>(g_part)[i];
    const float4 s1 = reinterpret_cast<const float4*>(g_part)[BB * CC * CC / 4 + i];

    const float mur = smu[r];
    float4 o;
    o.x = (s0.x + s1.x) * inv - mur * smu[c + 0];
    o.y = (s0.y + s1.y) * inv - mur * smu[c + 1];
    o.z = (s0.z + s1.z) * inv - mur * smu[c + 2];
    o.w = (s0.w + s1.w) * inv - mur * smu[c + 3];
    reinterpret_cast<float4*>(out)[i] = o;
}

// ---------------------------------------------------------------------------
extern "C" void kernel_launch(void* const* d_in, const int* in_sizes, int n_in,
                              void* d_out, int out_size) {
    const float* x = (const float*)d_in[0];
    float* out = (float*)d_out;

    cudaFuncSetAttribute(syrk_mma, cudaFuncAttributeMaxDynamicSharedMemorySize,
                         SMEM_BYTES);

    dim3 grid(KS, BB);
    syrk_mma<<<grid, 256, SMEM_BYTES>>>(x);
    finalize<<<(BB * CC * CC / 4) / 256, 256>>>(out);
}

// round 14
// speedup vs baseline: 1.2556x; 1.1541x over previous
#include <cuda_runtime.h>
#include <cstdint>

// Problem constants: B=64, C=128, M=H*W=4096, fp32 in/out
#define BB 64
#define CC 128
#define MM 4096
#define KS 2                    // split-K across CTAs
#define KCHUNK (MM / KS)        // 2048
#define KTILE 64                // bf16 k per stage
#define NSTAGE (KCHUNK / KTILE) // 32
#define PITCH 144               // smem row pitch bytes (128B data + 16B pad)
#define TILEB (CC * PITCH)      // 18432 bytes per bf16 tile
#define SPITCH 72               // transpose buffer pitch (floats)
#define SMEM_BYTES (4 * TILEB)  // 73728: 2 bufs x (hi+lo); S overlay fits

// ---------------- scratch (__device__ globals; no allocs allowed) ----------
__device__ float g_sum[KS * BB * CC];            // per-(ks,b,c) row sums
__device__ float g_part[KS * BB * CC * CC];      // per-ks S = P + Q + Q^T

// ---------------- helpers ---------------------------------------------------
__device__ __forceinline__ uint32_t smem_u32(const void* p) {
    uint32_t a;
    asm("{ .reg .u64 t; cvta.to.shared.u64 t, %1; cvt.u32.u64 %0, t; }"
        : "=r"(a) : "l"(p));
    return a;
}
__device__ __forceinline__ void ldsm_x4(uint32_t& r0, uint32_t& r1,
                                        uint32_t& r2, uint32_t& r3, uint32_t a) {
    asm volatile("ldmatrix.sync.aligned.m8n8.x4.shared.b16 {%0,%1,%2,%3}, [%4];"
                 : "=r"(r0), "=r"(r1), "=r"(r2), "=r"(r3) : "r"(a));
}
__device__ __forceinline__ void mma_bf16(float* d, const uint32_t* a,
                                         uint32_t b0, uint32_t b1) {
    asm volatile(
        "mma.sync.aligned.m16n8k16.row.col.f32.bf16.bf16.f32 "
        "{%0,%1,%2,%3}, {%4,%5,%6,%7}, {%8,%9}, {%0,%1,%2,%3};"
        : "+f"(d[0]), "+f"(d[1]), "+f"(d[2]), "+f"(d[3])
        : "r"(a[0]), "r"(a[1]), "r"(a[2]), "r"(a[3]), "r"(b0), "r"(b1));
}

// convert one float4 (4 elems of a row) to hi/lo bf16 pairs and store to smem
__device__ __forceinline__ void convert_store(const float4 xv, int row, int kseg,
                                              uint32_t hibase, uint32_t lobase,
                                              float& rsum) {
    rsum += (xv.x + xv.y) + (xv.z + xv.w);
    uint32_t h01, h23, l01, l23;
    asm("cvt.rn.bf16x2.f32 %0, %1, %2;" : "=r"(h01) : "f"(xv.y), "f"(xv.x));
    asm("cvt.rn.bf16x2.f32 %0, %1, %2;" : "=r"(h23) : "f"(xv.w), "f"(xv.z));
    const float hx = __uint_as_float(h01 << 16);
    const float hy = __uint_as_float(h01 & 0xffff0000u);
    const float hz = __uint_as_float(h23 << 16);
    const float hw = __uint_as_float(h23 & 0xffff0000u);
    asm("cvt.rn.bf16x2.f32 %0, %1, %2;" : "=r"(l01) : "f"(xv.y - hy), "f"(xv.x - hx));
    asm("cvt.rn.bf16x2.f32 %0, %1, %2;" : "=r"(l23) : "f"(xv.w - hw), "f"(xv.z - hz));
    const uint32_t off = (uint32_t)row * PITCH + (uint32_t)kseg * 8;
    asm volatile("st.shared.v2.b32 [%0], {%1,%2};"
                 :: "r"(hibase + off), "r"(h01), "r"(h23));
    asm volatile("st.shared.v2.b32 [%0], {%1,%2};"
                 :: "r"(lobase + off), "r"(l01), "r"(l23));
}

// ---------------------------------------------------------------------------
// SYRK via bf16-split mma.sync, two-term (P = hi*hi^T, Q = hi*lo^T).
// Round-8 skeleton (256 thr, 8 warps, 32x64 tiles, 1 barrier/stage) with
// STAGGERED convert order: each warp-group converts its own 64-row half of
// the NEXT stage's tile (8 float4/thread, same as R8); group (s&1) converts
// before its MMAs, the other group after. Each SMSP holds one warp of each
// group, so the tensor pipe is fed while the partner warp converts.
// grid = (KS, BB).
// ---------------------------------------------------------------------------
__global__ void __launch_bounds__(256, 1) syrk_mma(const float* __restrict__ x) {
    extern __shared__ __align__(128) uint8_t smraw[];
    uint8_t (*tiles)[2 * TILEB] = reinterpret_cast<uint8_t (*)[2 * TILEB]>(smraw);
    float (*S)[SPITCH] = reinterpret_cast<float (*)[SPITCH]>(smraw);

    const int tid = threadIdx.x;
    const int wid = tid >> 5;
    const int lid = tid & 31;
    const int group = tid >> 7;       // 0: warps 0-3 (rows 0-63), 1: warps 4-7
    const int b = blockIdx.y;
    const int ks = blockIdx.x;
    const float* xb = x + (size_t)b * CC * MM + ks * KCHUNK;

    const int rw = (wid >> 1) * 32;   // warp row base in 128x128 output
    const int cw = (wid & 1) * 64;    // warp col base

    float accP[2][8][4], accQ[2][8][4];
    #pragma unroll
    for (int mb = 0; mb < 2; mb++)
        #pragma unroll
        for (int jb = 0; jb < 8; jb++)
            #pragma unroll
            for (int q = 0; q < 4; q++) { accP[mb][jb][q] = 0.0f; accQ[mb][jb][q] = 0.0f; }

    float rs[8];
    #pragma unroll
    for (int i = 0; i < 8; i++) rs[i] = 0.f;

    // convert mapping: group covers rows [group*64, group*64+64).
    // thread: 16 ksegs x 8 row-subgroups; iteration it -> row base + it*8 + rowg8
    const int gt = tid & 127;
    const int rowg8 = gt >> 4;        // 0..7
    const int kseg = gt & 15;         // 0..15
    const int rbase = group * 64;

    // ldmatrix lane byte-offsets inside a tile
    const uint32_t a_row_off = ((lid & 7) + ((lid >> 3) & 1) * 8) * PITCH
                             + ((lid >> 4) * 8) * 2;
    const uint32_t b4_row_off = ((lid & 7) + (lid >> 4) * 8) * PITCH
                              + (((lid >> 3) & 1) * 8) * 2;

    // ---- prologue: both groups convert their half of stage 0 into buf0 -----
    float4 v[8];
    #pragma unroll
    for (int it = 0; it < 8; it++)
        v[it] = *reinterpret_cast<const float4*>(
            xb + (size_t)(rbase + it * 8 + rowg8) * MM + kseg * 4);
    {
        const uint32_t h0 = smem_u32(&tiles[0][0]);
        const uint32_t l0 = h0 + TILEB;
        #pragma unroll
        for (int it = 0; it < 8; it++)
            convert_store(v[it], rbase + it * 8 + rowg8, kseg, h0, l0, rs[it]);
    }
    // load stage 1 into v
    #pragma unroll
    for (int it = 0; it < 8; it++)
        v[it] = *reinterpret_cast<const float4*>(
            xb + (size_t)(rbase + it * 8 + rowg8) * MM + KTILE + kseg * 4);
    __syncthreads();

    for (int s = 0; s < NSTAGE; s++) {
        const int buf = s & 1;
        const uint32_t hibase = smem_u32(&tiles[buf][0]);
        const uint32_t lobase = hibase + TILEB;
        const uint32_t nhib = smem_u32(&tiles[buf ^ 1][0]);
        const uint32_t nlob = nhib + TILEB;
        const bool do_conv = (s + 1 < NSTAGE);
        const bool conv_first = (group == (s & 1));

        if (conv_first && do_conv) {
            #pragma unroll
            for (int it = 0; it < 8; it++)
                convert_store(v[it], rbase + it * 8 + rowg8, kseg,
                              nhib, nlob, rs[it]);
            if (s + 2 < NSTAGE) {
                const int k0 = (s + 2) * KTILE;
                #pragma unroll
                for (int it = 0; it < 8; it++)
                    v[it] = *reinterpret_cast<const float4*>(
                        xb + (size_t)(rbase + it * 8 + rowg8) * MM + k0 + kseg * 4);
            }
        }

        // 4 k16 MMA blocks on buf
        #pragma unroll
        for (int kb = 0; kb < 4; kb++) {
            uint32_t ah[2][4];
            #pragma unroll
            for (int mb = 0; mb < 2; mb++) {
                const uint32_t aoff = (rw + mb * 16) * PITCH + kb * 32 + a_row_off;
                ldsm_x4(ah[mb][0], ah[mb][1], ah[mb][2], ah[mb][3], hibase + aoff);
            }
            #pragma unroll
            for (int jbp = 0; jbp < 4; jbp++) {
                const uint32_t boff = (cw + jbp * 16) * PITCH + kb * 32 + b4_row_off;
                uint32_t bh0, bh1, bh2, bh3, bl0, bl1, bl2, bl3;
                ldsm_x4(bh0, bh1, bh2, bh3, hibase + boff);
                ldsm_x4(bl0, bl1, bl2, bl3, lobase + boff);
                #pragma unroll
                for (int mb = 0; mb < 2; mb++) {
                    mma_bf16(accP[mb][2 * jbp + 0], ah[mb], bh0, bh1);
                    mma_bf16(accP[mb][2 * jbp + 1], ah[mb], bh2, bh3);
                    mma_bf16(accQ[mb][2 * jbp + 0], ah[mb], bl0, bl1);
                    mma_bf16(accQ[mb][2 * jbp + 1], ah[mb], bl2, bl3);
                }
            }
        }

        if (!conv_first && do_conv) {
            #pragma unroll
            for (int it = 0; it < 8; it++)
                convert_store(v[it], rbase + it * 8 + rowg8, kseg,
                              nhib, nlob, rs[it]);
            if (s + 2 < NSTAGE) {
                const int k0 = (s + 2) * KTILE;
                #pragma unroll
                for (int it = 0; it < 8; it++)
                    v[it] = *reinterpret_cast<const float4*>(
                        xb + (size_t)(rbase + it * 8 + rowg8) * MM + k0 + kseg * 4);
            }
        }
        __syncthreads();
    }

    // row sums: 16 lanes (same rowg8) share a row; reduce over kseg
    #pragma unroll
    for (int it = 0; it < 8; it++) {
        float vv = rs[it];
        vv += __shfl_xor_sync(0xffffffffu, vv, 8);
        vv += __shfl_xor_sync(0xffffffffu, vv, 4);
        vv += __shfl_xor_sync(0xffffffffu, vv, 2);
        vv += __shfl_xor_sync(0xffffffffu, vv, 1);
        if (kseg == 0)
            g_sum[ks * BB * CC + b * CC + rbase + it * 8 + rowg8] = vv;
    }

    // ---- Q + Q^T fold via smem transpose (2 column-half phases) ------------
    const int g = lid >> 2;            // 0..7
    const int tg = lid & 3;            // 0..3
    __syncthreads();                   // last-stage ldsm done before S overlay
    #pragma unroll
    for (int h = 0; h < 2; h++) {
        if ((wid & 1) == h) {
            #pragma unroll
            for (int mb = 0; mb < 2; mb++)
                #pragma unroll
                for (int jb = 0; jb < 8; jb++) {
                    const int row = rw + mb * 16 + g;
                    const int cl = jb * 8 + tg * 2;
                    S[row][cl]         = accQ[mb][jb][0];
                    S[row][cl + 1]     = accQ[mb][jb][1];
                    S[row + 8][cl]     = accQ[mb][jb][2];
                    S[row + 8][cl + 1] = accQ[mb][jb][3];
                }
        }
        __syncthreads();
        if ((wid >> 2) == h) {
            #pragma unroll
            for (int mb = 0; mb < 2; mb++)
                #pragma unroll
                for (int jb = 0; jb < 8; jb++) {
                    const int C = cw + jb * 8 + tg * 2;
                    const int R0 = (rw + mb * 16 + g) & 63;
                    accP[mb][jb][0] += S[C][R0];
                    accP[mb][jb][1] += S[C + 1][R0];
                    accP[mb][jb][2] += S[C][R0 + 8];
                    accP[mb][jb][3] += S[C + 1][R0 + 8];
                }
        }
        __syncthreads();
    }

    // epilogue: write S = P + Q^T(accumulated) + Q
    float* dst = g_part + (size_t)(ks * BB + b) * (CC * CC);
    #pragma unroll
    for (int mb = 0; mb < 2; mb++) {
        #pragma unroll
        for (int jb = 0; jb < 8; jb++) {
            const int row = rw + mb * 16 + g;
            const int col = cw + jb * 8 + tg * 2;
            *reinterpret_cast<float2*>(&dst[(size_t)row * CC + col]) =
                make_float2(accP[mb][jb][0] + accQ[mb][jb][0],
                            accP[mb][jb][1] + accQ[mb][jb][1]);
            *reinterpret_cast<float2*>(&dst[(size_t)(row + 8) * CC + col]) =
                make_float2(accP[mb][jb][2] + accQ[mb][jb][2],
                            accP[mb][jb][3] + accQ[mb][jb][3]);
        }
    }
}

// ---------------------------------------------------------------------------
// out[b][r][c] = (S0 + S1)/M - mu_r * mu_c  (per-block smem-cached mu)
// ---------------------------------------------------------------------------
__global__ void __launch_bounds__(256) finalize(float* __restrict__ out) {
    __shared__ float smu[CC];
    const int i = blockIdx.x * blockDim.x + threadIdx.x;    // float4 index
    const int base = i * 4;
    const int b = base >> 14;                                // fixed per block
    const float inv = 1.0f / (float)MM;

    if (threadIdx.x < CC)
        smu[threadIdx.x] = (g_sum[b * CC + threadIdx.x]
                          + g_sum[BB * CC + b * CC + threadIdx.x]) * inv;
    __syncthreads();

    const int r = (base >> 7) & (CC - 1);
    const int c = base & (CC - 1);

    const float4 s0 = reinterpret_cast<const float4*>(g_part)[i];
    const float4 s1 = reinterpret_cast<const float4*>(g_part)[BB * CC * CC / 4 + i];

    const float mur = smu[r];
    float4 o;
    o.x = (s0.x + s1.x) * inv - mur * smu[c + 0];
    o.y = (s0.y + s1.y) * inv - mur * smu[c + 1];
    o.z = (s0.z + s1.z) * inv - mur * smu[c + 2];
    o.w = (s0.w + s1.w) * inv - mur * smu[c + 3];
    reinterpret_cast<float4*>(out)[i] = o;
}

// ---------------------------------------------------------------------------
extern "C" void kernel_launch(void* const* d_in, const int* in_sizes, int n_in,
                              void* d_out, int out_size) {
    const float* x = (const float*)d_in[0];
    float* out = (float*)d_out;

    cudaFuncSetAttribute(syrk_mma, cudaFuncAttributeMaxDynamicSharedMemorySize,
                         SMEM_BYTES);

    dim3 grid(KS, BB);
    syrk_mma<<<grid, 256, SMEM_BYTES>>>(x);
    finalize<<<(BB * CC * CC / 4) / 256, 256>>>(out);
}

// round 15
// speedup vs baseline: 1.3081x; 1.0418x over previous
#include <cuda_runtime.h>
#include <cstdint>

// Problem constants: B=64, C=128, M=H*W=4096, fp32 in/out
#define BB 64
#define CC 128
#define MM 4096
#define KS 2                    // split-K across CTAs
#define KCHUNK (MM / KS)        // 2048
#define KTILE 64                // bf16 k per stage
#define NSTAGE (KCHUNK / KTILE) // 32
#define PITCH 144               // smem row pitch bytes (128B data + 16B pad)
#define TILEB (CC * PITCH)      // 18432 bytes per bf16 tile
#define SPITCH 72               // transpose buffer pitch (floats)
#define SMEM_BYTES (4 * TILEB)  // 73728: 2 bufs x (hi+lo); S overlay fits

// ---------------- scratch (__device__ globals; no allocs allowed) ----------
__device__ float g_sum[KS * BB * CC];            // per-(ks,b,c) row sums
__device__ float g_part[KS * BB * CC * CC];      // per-ks S = P + Q + Q^T

// ---------------- helpers ---------------------------------------------------
__device__ __forceinline__ uint32_t smem_u32(const void* p) {
    uint32_t a;
    asm("{ .reg .u64 t; cvta.to.shared.u64 t, %1; cvt.u32.u64 %0, t; }"
        : "=r"(a) : "l"(p));
    return a;
}
__device__ __forceinline__ void ldsm_x4(uint32_t& r0, uint32_t& r1,
                                        uint32_t& r2, uint32_t& r3, uint32_t a) {
    asm volatile("ldmatrix.sync.aligned.m8n8.x4.shared.b16 {%0,%1,%2,%3}, [%4];"
                 : "=r"(r0), "=r"(r1), "=r"(r2), "=r"(r3) : "r"(a));
}
__device__ __forceinline__ void mma_bf16(float* d, const uint32_t* a,
                                         uint32_t b0, uint32_t b1) {
    asm volatile(
        "mma.sync.aligned.m16n8k16.row.col.f32.bf16.bf16.f32 "
        "{%0,%1,%2,%3}, {%4,%5,%6,%7}, {%8,%9}, {%0,%1,%2,%3};"
        : "+f"(d[0]), "+f"(d[1]), "+f"(d[2]), "+f"(d[3])
        : "r"(a[0]), "r"(a[1]), "r"(a[2]), "r"(a[3]), "r"(b0), "r"(b1));
}

// convert one float4 (4 elems of a row) to hi/lo bf16 pairs and store to smem
__device__ __forceinline__ void convert_store(const float4 xv, int row, int kseg,
                                              uint32_t hibase, uint32_t lobase,
                                              float& rsum) {
    rsum += (xv.x + xv.y) + (xv.z + xv.w);
    uint32_t h01, h23, l01, l23;
    asm("cvt.rn.bf16x2.f32 %0, %1, %2;" : "=r"(h01) : "f"(xv.y), "f"(xv.x));
    asm("cvt.rn.bf16x2.f32 %0, %1, %2;" : "=r"(h23) : "f"(xv.w), "f"(xv.z));
    const float hx = __uint_as_float(h01 << 16);
    const float hy = __uint_as_float(h01 & 0xffff0000u);
    const float hz = __uint_as_float(h23 << 16);
    const float hw = __uint_as_float(h23 & 0xffff0000u);
    asm("cvt.rn.bf16x2.f32 %0, %1, %2;" : "=r"(l01) : "f"(xv.y - hy), "f"(xv.x - hx));
    asm("cvt.rn.bf16x2.f32 %0, %1, %2;" : "=r"(l23) : "f"(xv.w - hw), "f"(xv.z - hz));
    const uint32_t off = (uint32_t)row * PITCH + (uint32_t)kseg * 8;
    asm volatile("st.shared.v2.b32 [%0], {%1,%2};"
                 :: "r"(hibase + off), "r"(h01), "r"(h23));
    asm volatile("st.shared.v2.b32 [%0], {%1,%2};"
                 :: "r"(lobase + off), "r"(l01), "r"(l23));
}

// ---------------------------------------------------------------------------
// SYRK via bf16-split mma.sync, two-term (P = hi*hi^T, Q = hi*lo^T).
// R8 skeleton (256 thr, 8 warps, 1 barrier/stage, phase-separated convert)
// with A-HEAVY 64x32 warp tiles: per kb only 8 ldmatrix.x4 (4 A-hi + 2 B-hi
// + 2 B-lo) feed 32 MMAs, cutting smem-crossbar LDSM bytes by 20% vs 32x64.
// Q + Q^T folded in-CTA via smem transpose (2 column-half phases).
// grid = (KS, BB).
// ---------------------------------------------------------------------------
__global__ void __launch_bounds__(256, 1) syrk_mma(const float* __restrict__ x) {
    extern __shared__ __align__(128) uint8_t smraw[];
    uint8_t (*tiles)[2 * TILEB] = reinterpret_cast<uint8_t (*)[2 * TILEB]>(smraw);
    float (*S)[SPITCH] = reinterpret_cast<float (*)[SPITCH]>(smraw);

    const int tid = threadIdx.x;
    const int wid = tid >> 5;
    const int lid = tid & 31;
    const int b = blockIdx.y;
    const int ks = blockIdx.x;
    const float* xb = x + (size_t)b * CC * MM + ks * KCHUNK;

    const int rw = (wid & 1) * 64;    // warp row base (64-row tile)
    const int cw = (wid >> 1) * 32;   // warp col base (32-col tile)

    float accP[4][4][4], accQ[4][4][4];
    #pragma unroll
    for (int mb = 0; mb < 4; mb++)
        #pragma unroll
        for (int jb = 0; jb < 4; jb++)
            #pragma unroll
            for (int q = 0; q < 4; q++) { accP[mb][jb][q] = 0.0f; accQ[mb][jb][q] = 0.0f; }

    float rs[8];
    #pragma unroll
    for (int i = 0; i < 8; i++) rs[i] = 0.f;

    // loader mapping: 16 k-segments (float4) per row, 16 row groups of 8 rows
    const int rowg = tid >> 4;        // 0..15
    const int kseg = tid & 15;        // 0..15

    // ldmatrix lane byte-offsets inside a tile
    const uint32_t a_row_off = ((lid & 7) + ((lid >> 3) & 1) * 8) * PITCH
                             + ((lid >> 4) * 8) * 2;
    const uint32_t b4_row_off = ((lid & 7) + (lid >> 4) * 8) * PITCH
                              + (((lid >> 3) & 1) * 8) * 2;

    float4 v[8];
    #pragma unroll
    for (int it = 0; it < 8; it++)
        v[it] = *reinterpret_cast<const float4*>(
            xb + (size_t)(it * 16 + rowg) * MM + kseg * 4);

    for (int s = 0; s < NSTAGE; s++) {
        const int buf = s & 1;
        const uint32_t hibase = smem_u32(&tiles[buf][0]);
        const uint32_t lobase = hibase + TILEB;

        // convert current regs -> smem tiles, accumulate row sums
        #pragma unroll
        for (int it = 0; it < 8; it++)
            convert_store(v[it], it * 16 + rowg, kseg, hibase, lobase, rs[it]);
        // Single barrier per stage (double buffering covers the WAR hazard).
        __syncthreads();

        // issue next stage's global loads now: a full stage of latency cover
        if (s + 1 < NSTAGE) {
            const int k0 = (s + 1) * KTILE;
            #pragma unroll
            for (int it = 0; it < 8; it++)
                v[it] = *reinterpret_cast<const float4*>(
                    xb + (size_t)(it * 16 + rowg) * MM + k0 + kseg * 4);
        }

        // compute: 4 k16 steps; A (hi) covers 64 rows, B covers 32 cols
        #pragma unroll
        for (int kb = 0; kb < 4; kb++) {
            uint32_t ah[4][4];
            #pragma unroll
            for (int mb = 0; mb < 4; mb++) {
                const uint32_t aoff = (rw + mb * 16) * PITCH + kb * 32 + a_row_off;
                ldsm_x4(ah[mb][0], ah[mb][1], ah[mb][2], ah[mb][3], hibase + aoff);
            }
            #pragma unroll
            for (int jp = 0; jp < 2; jp++) {
                const uint32_t boff = (cw + jp * 16) * PITCH + kb * 32 + b4_row_off;
                uint32_t bh0, bh1, bh2, bh3, bl0, bl1, bl2, bl3;
                ldsm_x4(bh0, bh1, bh2, bh3, hibase + boff);
                ldsm_x4(bl0, bl1, bl2, bl3, lobase + boff);
                #pragma unroll
                for (int mb = 0; mb < 4; mb++) {
                    mma_bf16(accP[mb][2 * jp + 0], ah[mb], bh0, bh1);
                    mma_bf16(accP[mb][2 * jp + 1], ah[mb], bh2, bh3);
                    mma_bf16(accQ[mb][2 * jp + 0], ah[mb], bl0, bl1);
                    mma_bf16(accQ[mb][2 * jp + 1], ah[mb], bl2, bl3);
                }
            }
        }
    }

    // row sums: 16 lanes (same rowg) share a row; reduce over kseg, store per ks
    #pragma unroll
    for (int it = 0; it < 8; it++) {
        float vv = rs[it];
        vv += __shfl_xor_sync(0xffffffffu, vv, 8);
        vv += __shfl_xor_sync(0xffffffffu, vv, 4);
        vv += __shfl_xor_sync(0xffffffffu, vv, 2);
        vv += __shfl_xor_sync(0xffffffffu, vv, 1);
        if (kseg == 0)
            g_sum[ks * BB * CC + b * CC + it * 16 + rowg] = vv;
    }

    // ---- Q + Q^T fold via smem transpose (2 column-half phases) ------------
    // phase h: writers = column-half warps (wid>>2 == h) store their accQ
    //          (cols [h*64, h*64+64) mapped to S[row][col - h*64]);
    //          consumers = row-half warps (wid&1 == h) add the transpose.
    const int g = lid >> 2;            // 0..7
    const int tg = lid & 3;            // 0..3
    __syncthreads();                   // last-stage ldsm done before S overlay
    #pragma unroll
    for (int h = 0; h < 2; h++) {
        if ((wid >> 2) == h) {
            #pragma unroll
            for (int mb = 0; mb < 4; mb++)
                #pragma unroll
                for (int jb = 0; jb < 4; jb++) {
                    const int row = rw + mb * 16 + g;
                    const int cl = (cw & 63) + jb * 8 + tg * 2;
                    S[row][cl]         = accQ[mb][jb][0];
                    S[row][cl + 1]     = accQ[mb][jb][1];
                    S[row + 8][cl]     = accQ[mb][jb][2];
                    S[row + 8][cl + 1] = accQ[mb][jb][3];
                }
        }
        __syncthreads();
        if ((wid & 1) == h) {
            #pragma unroll
            for (int mb = 0; mb < 4; mb++)
                #pragma unroll
                for (int jb = 0; jb < 4; jb++) {
                    const int C = cw + jb * 8 + tg * 2;
                    const int R0 = mb * 16 + g;       // (rw+mb*16+g) - h*64
                    accP[mb][jb][0] += S[C][R0];
                    accP[mb][jb][1] += S[C + 1][R0];
                    accP[mb][jb][2] += S[C][R0 + 8];
                    accP[mb][jb][3] += S[C + 1][R0 + 8];
                }
        }
        __syncthreads();
    }

    // epilogue: write S = P + Q^T(accumulated) + Q
    float* dst = g_part + (size_t)(ks * BB + b) * (CC * CC);
    #pragma unroll
    for (int mb = 0; mb < 4; mb++) {
        #pragma unroll
        for (int jb = 0; jb < 4; jb++) {
            const int row = rw + mb * 16 + g;
            const int col = cw + jb * 8 + tg * 2;
            *reinterpret_cast<float2*>(&dst[(size_t)row * CC + col]) =
                make_float2(accP[mb][jb][0] + accQ[mb][jb][0],
                            accP[mb][jb][1] + accQ[mb][jb][1]);
            *reinterpret_cast<float2*>(&dst[(size_t)(row + 8) * CC + col]) =
                make_float2(accP[mb][jb][2] + accQ[mb][jb][2],
                            accP[mb][jb][3] + accQ[mb][jb][3]);
        }
    }
}

// ---------------------------------------------------------------------------
// out[b][r][c] = (S0 + S1)/M - mu_r * mu_c  (per-block smem-cached mu)
// ---------------------------------------------------------------------------
__global__ void __launch_bounds__(256) finalize(float* __restrict__ out) {
    __shared__ float smu[CC];
    const int i = blockIdx.x * blockDim.x + threadIdx.x;    // float4 index
    const int base = i * 4;
    const int b = base >> 14;                                // fixed per block
    const float inv = 1.0f / (float)MM;

    if (threadIdx.x < CC)
        smu[threadIdx.x] = (g_sum[b * CC + threadIdx.x]
                          + g_sum[BB * CC + b * CC + threadIdx.x]) * inv;
    __syncthreads();

    const int r = (base >> 7) & (CC - 1);
    const int c = base & (CC - 1);

    const float4 s0 = reinterpret_cast<const float4*>(g_part)[i];
    const float4 s1 = reinterpret_cast<const float4*>(g_part)[BB * CC * CC / 4 + i];

    const float mur = smu[r];
    float4 o;
    o.x = (s0.x + s1.x) * inv - mur * smu[c + 0];
    o.y = (s0.y + s1.y) * inv - mur * smu[c + 1];
    o.z = (s0.z + s1.z) * inv - mur * smu[c + 2];
    o.w = (s0.w + s1.w) * inv - mur * smu[c + 3];
    reinterpret_cast<float4*>(out)[i] = o;
}

// ---------------------------------------------------------------------------
extern "C" void kernel_launch(void* const* d_in, const int* in_sizes, int n_in,
                              void* d_out, int out_size) {
    const float* x = (const float*)d_in[0];
    float* out = (float*)d_out;

    cudaFuncSetAttribute(syrk_mma, cudaFuncAttributeMaxDynamicSharedMemorySize,
                         SMEM_BYTES);

    dim3 grid(KS, BB);
    syrk_mma<<<grid, 256, SMEM_BYTES>>>(x);
    finalize<<<(BB * CC * CC / 4) / 256, 256>>>(out);
}